// round 2
// baseline (speedup 1.0000x reference)
#include <cuda_runtime.h>
#include <mma.h>
using namespace nvcuda;

// Problem dims
#define BB 16
#define LL 50
#define PP 49
#define TT 20
#define DD 512
#define HH 8
#define DHD 64
#define DFF 2048
#define NBL (BB*LL)          // 800
#define M_IMG (NBL*TT)       // 16000  (mult of 128: 16000/128=125)
#define M_TIT (NBL*PP)       // 39200
#define M_TIT_PAD 39296      // mult of 128 (307*128)
#define M_ALL (M_IMG + M_TIT_PAD)   // 55296 = 432*128

// Scratch (zero-init; pad rows of g_attn never written -> stay 0)
__device__ float g_attn[(size_t)M_ALL*DD];
__device__ float g_hid [(size_t)M_ALL*DD];
__device__ float g_G   [(size_t)M_TIT_PAD*DFF];
__device__ float g_F   [(size_t)M_ALL*DD];

// ---------------------------------------------------------------------------
// Attention kernel: one block per (bl, h). Exact fp32.
// ---------------------------------------------------------------------------
__global__ void __launch_bounds__(256) attn_kernel(
    const float* __restrict__ img, const float* __restrict__ tit,
    const int* __restrict__ mask,
    const float* __restrict__ scale_img, const float* __restrict__ scale_tit,
    float* __restrict__ attnI, float* __restrict__ attnT)
{
    __shared__ float simg[PP][DHD+1];
    __shared__ float stit[TT][DHD+1];
    __shared__ float raw[PP][TT];
    __shared__ float pimg[PP][TT];
    __shared__ float ptit[TT][PP];
    __shared__ float sci[PP];
    __shared__ float sct[TT];
    __shared__ int   smask[TT];

    int bl = blockIdx.x >> 3;
    int h  = blockIdx.x & 7;
    int tid = threadIdx.x;

    const float* ib = img + (size_t)bl*PP*DD + h*DHD;
    const float* tb = tit + (size_t)bl*TT*DD + h*DHD;

    for (int i = tid; i < PP*DHD; i += 256) { int p=i>>6, d=i&63; simg[p][d] = ib[p*DD+d]; }
    for (int i = tid; i < TT*DHD; i += 256) { int t=i>>6, d=i&63; stit[t][d] = tb[t*DD+d]; }
    if (tid < TT) { smask[tid] = mask[bl*TT+tid]; sct[tid] = scale_tit[h*TT+tid]; }
    if (tid >= 64 && tid < 64+PP) sci[tid-64] = scale_img[h*PP + (tid-64)];
    __syncthreads();

    for (int i = tid; i < PP*TT; i += 256) {
        int p = i / TT, t = i - p*TT;
        float s = 0.f;
        #pragma unroll
        for (int d = 0; d < DHD; d++) s += simg[p][d]*stit[t][d];
        raw[p][t] = s * 0.125f;
    }
    __syncthreads();

    if (tid < PP) {
        int p = tid; float sc = sci[p];
        float v[TT]; float mx = -INFINITY;
        #pragma unroll
        for (int t = 0; t < TT; t++) { v[t] = smask[t] ? raw[p][t]*sc : -1e9f; mx = fmaxf(mx, v[t]); }
        float sum = 0.f;
        #pragma unroll
        for (int t = 0; t < TT; t++) { v[t] = __expf(v[t]-mx); sum += v[t]; }
        float inv = 1.f/sum;
        #pragma unroll
        for (int t = 0; t < TT; t++) pimg[p][t] = v[t]*inv;
    } else if (tid >= 64 && tid < 64+TT) {
        int t = tid-64; float sc = sct[t];
        if (smask[t]) {
            float mx = -INFINITY;
            for (int p = 0; p < PP; p++) mx = fmaxf(mx, raw[p][t]*sc);
            float sum = 0.f;
            for (int p = 0; p < PP; p++) { float e = __expf(raw[p][t]*sc - mx); ptit[t][p] = e; sum += e; }
            float inv = 1.f/sum;
            for (int p = 0; p < PP; p++) ptit[t][p] *= inv;
        } else {
            float u = 1.0f/(float)PP;
            for (int p = 0; p < PP; p++) ptit[t][p] = u;
        }
    }
    __syncthreads();

    for (int i = tid; i < TT*DHD; i += 256) {
        int t = i>>6, d = i&63;
        float s = 0.f;
        #pragma unroll
        for (int p = 0; p < PP; p++) s += ptit[t][p]*simg[p][d];
        attnI[((size_t)bl*TT + t)*DD + h*DHD + d] = s;
    }
    for (int i = tid; i < PP*DHD; i += 256) {
        int p = i>>6, d = i&63;
        float s = 0.f;
        #pragma unroll
        for (int t = 0; t < TT; t++) s += pimg[p][t]*stit[t][d];
        attnT[((size_t)bl*PP + p)*DD + h*DHD + d] = s;
    }
}

// ---------------------------------------------------------------------------
// tf32 WMMA GEMM: C[M,N] = A[M,K] @ W[N,K]^T + bias (optional gelu)
// BM=128 BN=128 BK=32, double-buffered cp.async, 8 warps (4x2), warp tile 32x64.
// M%128==0, N%128==0, K%32==0.
// ---------------------------------------------------------------------------
#define BM 128
#define BN 128
#define BK 32
#define AST 36   // smem row stride (floats)
#define CST 20
#define SMEM_BYTES (4u * (2*BM*AST + 2*BN*AST))   // 73728

__device__ __forceinline__ void cp16(float* s, const float* g) {
    unsigned sa = (unsigned)__cvta_generic_to_shared(s);
    asm volatile("cp.async.cg.shared.global [%0], [%1], 16;\n" :: "r"(sa), "l"(g));
}

__device__ __forceinline__ float gelu_tanh_f(float x) {
    return 0.5f*x*(1.f + tanhf(0.79788456080286536f*(x + 0.044715f*x*x*x)));
}

template<int GELU_EPI>
__global__ void __launch_bounds__(256) gemm_tf32(
    const float* __restrict__ A, const float* __restrict__ W,
    const float* __restrict__ bias, float* __restrict__ C,
    int M, int N, int K)
{
    extern __shared__ float smem[];
    float* As = smem;                  // 2 stages of BM*AST
    float* Bs = smem + 2*BM*AST;       // 2 stages of BN*AST

    int tid  = threadIdx.x;
    int warp = tid >> 5, lane = tid & 31;
    int wm = warp >> 1, wn = warp & 1;          // 4x2 warp grid
    long m0 = (long)blockIdx.y * BM;
    long n0 = (long)blockIdx.x * BN;

    const float* Ag = A + m0*(long)K;
    const float* Wg = W + n0*(long)K;

    int lr = tid >> 3;          // 0..31
    int lc = (tid & 7) << 2;    // 0..28

    wmma::fragment<wmma::accumulator,16,16,8,float> acc[2][4];
    #pragma unroll
    for (int i = 0; i < 2; i++)
        #pragma unroll
        for (int j = 0; j < 4; j++) wmma::fill_fragment(acc[i][j], 0.f);

    int nk = K / BK;

    // prologue: stage 0
    {
        float* as = As; float* bs = Bs;
        #pragma unroll
        for (int r = 0; r < 4; r++) {
            cp16(as + (lr + r*32)*AST + lc, Ag + (long)(lr + r*32)*K + lc);
            cp16(bs + (lr + r*32)*AST + lc, Wg + (long)(lr + r*32)*K + lc);
        }
        asm volatile("cp.async.commit_group;\n");
    }

    for (int kt = 0; kt < nk; kt++) {
        int cur = kt & 1;
        if (kt + 1 < nk) {
            int nxt = cur ^ 1;
            int k0 = (kt+1)*BK;
            float* as = As + nxt*BM*AST;
            float* bs = Bs + nxt*BN*AST;
            #pragma unroll
            for (int r = 0; r < 4; r++) {
                cp16(as + (lr + r*32)*AST + lc, Ag + (long)(lr + r*32)*K + k0 + lc);
                cp16(bs + (lr + r*32)*AST + lc, Wg + (long)(lr + r*32)*K + k0 + lc);
            }
            asm volatile("cp.async.commit_group;\n");
            asm volatile("cp.async.wait_group 1;\n");
        } else {
            asm volatile("cp.async.wait_group 0;\n");
        }
        __syncthreads();

        const float* as = As + cur*BM*AST + (wm*32)*AST;
        const float* bs = Bs + cur*BN*AST + (wn*64)*AST;
        #pragma unroll
        for (int kk = 0; kk < BK; kk += 8) {
            wmma::fragment<wmma::matrix_a,16,16,8,wmma::precision::tf32,wmma::row_major> af[2];
            wmma::fragment<wmma::matrix_b,16,16,8,wmma::precision::tf32,wmma::col_major> bf[4];
            #pragma unroll
            for (int i = 0; i < 2; i++) {
                wmma::load_matrix_sync(af[i], as + i*16*AST + kk, AST);
                #pragma unroll
                for (int e = 0; e < af[i].num_elements; e++)
                    af[i].x[e] = wmma::__float_to_tf32(af[i].x[e]);
            }
            #pragma unroll
            for (int j = 0; j < 4; j++) {
                wmma::load_matrix_sync(bf[j], bs + j*16*AST + kk, AST);
                #pragma unroll
                for (int e = 0; e < bf[j].num_elements; e++)
                    bf[j].x[e] = wmma::__float_to_tf32(bf[j].x[e]);
            }
            #pragma unroll
            for (int i = 0; i < 2; i++)
                #pragma unroll
                for (int j = 0; j < 4; j++)
                    wmma::mma_sync(acc[i][j], af[i], bf[j], acc[i][j]);
        }
        __syncthreads();
    }

    // Epilogue: stage through smem (reuse As), bias + optional gelu
    float* cw = As + warp*16*CST;
    #pragma unroll
    for (int i = 0; i < 2; i++) {
        #pragma unroll
        for (int j = 0; j < 4; j++) {
            wmma::store_matrix_sync(cw, acc[i][j], CST, wmma::mem_row_major);
            __syncwarp();
            long gm = m0 + wm*32 + i*16;
            long gn = n0 + wn*64 + j*16;
            #pragma unroll
            for (int q = 0; q < 2; q++) {
                int idx = lane + q*32;
                int r  = idx >> 2;
                int c4 = (idx & 3) << 2;
                float4 v;
                float* src = cw + r*CST + c4;
                v.x = src[0] + bias[gn + c4 + 0];
                v.y = src[1] + bias[gn + c4 + 1];
                v.z = src[2] + bias[gn + c4 + 2];
                v.w = src[3] + bias[gn + c4 + 3];
                if (GELU_EPI) {
                    v.x = gelu_tanh_f(v.x); v.y = gelu_tanh_f(v.y);
                    v.z = gelu_tanh_f(v.z); v.w = gelu_tanh_f(v.w);
                }
                *(float4*)(C + (gm + r)*(long)N + gn + c4) = v;
            }
            __syncwarp();
        }
    }
}

// ---------------------------------------------------------------------------
// LayerNorm (ddof=1) + residual
// ---------------------------------------------------------------------------
__global__ void __launch_bounds__(128) ln_res_kernel(
    const float* __restrict__ F, const float* __restrict__ hid,
    const float* __restrict__ a, const float* __restrict__ b,
    float* __restrict__ out)
{
    int row = blockIdx.x;
    const float* x = F + (size_t)row*DD;
    int tid = threadIdx.x;
    float v[4]; float s = 0.f, ss = 0.f;
    #pragma unroll
    for (int k = 0; k < 4; k++) { v[k] = x[tid + k*128]; s += v[k]; ss += v[k]*v[k]; }
    #pragma unroll
    for (int o = 16; o; o >>= 1) { s += __shfl_xor_sync(~0u, s, o); ss += __shfl_xor_sync(~0u, ss, o); }
    __shared__ float sh[8];
    if ((tid & 31) == 0) { sh[tid>>5] = s; sh[4 + (tid>>5)] = ss; }
    __syncthreads();
    s  = sh[0]+sh[1]+sh[2]+sh[3];
    ss = sh[4]+sh[5]+sh[6]+sh[7];
    float mean = s * (1.f/512.f);
    float var  = fmaxf((ss - 512.f*mean*mean) * (1.f/511.f), 0.f);
    float inv  = 1.f/(sqrtf(var) + 1e-6f);
    const float* hh = hid + (size_t)row*DD;
    float* oo = out + (size_t)row*DD;
    #pragma unroll
    for (int k = 0; k < 4; k++) {
        int c = tid + k*128;
        oo[c] = hh[c] + a[c]*(v[k]-mean)*inv + b[c];
    }
}

// ---------------------------------------------------------------------------
// Launch
// ---------------------------------------------------------------------------
extern "C" void kernel_launch(void* const* d_in, const int* in_sizes, int n_in,
                              void* d_out, int out_size)
{
    const float* img         = (const float*)d_in[0];
    const float* title       = (const float*)d_in[1];
    const int*   mask        = (const int*)  d_in[2];
    const float* scale_img   = (const float*)d_in[3];
    const float* scale_title = (const float*)d_in[4];
    const float* w_proj      = (const float*)d_in[5];
    const float* b_proj      = (const float*)d_in[6];
    const float* w1_img      = (const float*)d_in[7];
    const float* b1_img      = (const float*)d_in[8];
    const float* w2_img      = (const float*)d_in[9];
    const float* b2_img      = (const float*)d_in[10];
    const float* w1_tit      = (const float*)d_in[11];
    const float* b1_tit      = (const float*)d_in[12];
    const float* w2_tit      = (const float*)d_in[13];
    const float* b2_tit      = (const float*)d_in[14];
    const float* ln_a_img    = (const float*)d_in[15];
    const float* ln_b_img    = (const float*)d_in[16];
    const float* ln_a_tit    = (const float*)d_in[17];
    const float* ln_b_tit    = (const float*)d_in[18];
    float* out = (float*)d_out;

    float *attn, *hid, *G, *F;
    cudaGetSymbolAddress((void**)&attn, g_attn);
    cudaGetSymbolAddress((void**)&hid,  g_hid);
    cudaGetSymbolAddress((void**)&G,    g_G);
    cudaGetSymbolAddress((void**)&F,    g_F);

    cudaFuncSetAttribute(gemm_tf32<0>, cudaFuncAttributeMaxDynamicSharedMemorySize, SMEM_BYTES);
    cudaFuncSetAttribute(gemm_tf32<1>, cudaFuncAttributeMaxDynamicSharedMemorySize, SMEM_BYTES);

    float* attnI = attn;
    float* attnT = attn + (size_t)M_IMG*DD;
    float* hidI  = hid;
    float* hidT  = hid + (size_t)M_IMG*DD;
    float* FI    = F;
    float* FT    = F + (size_t)M_IMG*DD;

    attn_kernel<<<NBL*HH, 256>>>(img, title, mask, scale_img, scale_title, attnI, attnT);

    // proj for BOTH streams in one GEMM: hid = attn @ w_proj^T + b_proj
    gemm_tf32<0><<<dim3(DD/BN,  M_ALL/BM), 256, SMEM_BYTES>>>(attn, w_proj, b_proj, hid, M_ALL, DD, DD);

    // img FFN
    gemm_tf32<1><<<dim3(DFF/BN, M_IMG/BM), 256, SMEM_BYTES>>>(hidI, w1_img, b1_img, G,  M_IMG, DFF, DD);
    gemm_tf32<0><<<dim3(DD/BN,  M_IMG/BM), 256, SMEM_BYTES>>>(G,    w2_img, b2_img, FI, M_IMG, DD,  DFF);
    // tit FFN (reuses G)
    gemm_tf32<1><<<dim3(DFF/BN, M_TIT_PAD/BM), 256, SMEM_BYTES>>>(hidT, w1_tit, b1_tit, G,  M_TIT_PAD, DFF, DD);
    gemm_tf32<0><<<dim3(DD/BN,  M_TIT_PAD/BM), 256, SMEM_BYTES>>>(G,    w2_tit, b2_tit, FT, M_TIT_PAD, DD,  DFF);

    // LN + residual -> outputs
    ln_res_kernel<<<M_IMG, 128>>>(FI, hidI, ln_a_img, ln_b_img, out);
    ln_res_kernel<<<M_TIT, 128>>>(FT, hidT, ln_a_tit, ln_b_tit, out + (size_t)M_IMG*DD);
}

// round 4
// speedup vs baseline: 1.8041x; 1.8041x over previous
#include <cuda_runtime.h>
#include <cstdint>

// Problem dims
#define BB 16
#define LL 50
#define PP 49
#define TT 20
#define DD 512
#define HH 8
#define DHD 64
#define DFF 2048
#define NBL (BB*LL)            // 800
#define M_IMG (NBL*TT)         // 16000
#define M_TIT (NBL*PP)         // 39200
#define M_IMG_PAD 16128        // 63*256
#define M_TIT_PAD 39424        // 154*256
#define M_ALL (M_IMG_PAD + M_TIT_PAD)   // 55552 = 217*256

// Scratch (zero-init; pad rows never written -> stay 0)
__device__ float g_attn[(size_t)M_ALL*DD];
__device__ float g_hid [(size_t)M_ALL*DD];
__device__ float g_G   [(size_t)M_TIT_PAD*DFF];
__device__ float g_F   [(size_t)M_ALL*DD];

// ---------------------------------------------------------------------------
// helpers
// ---------------------------------------------------------------------------
__device__ __forceinline__ void cp16(void* s, const void* g) {
    unsigned sa = (unsigned)__cvta_generic_to_shared(s);
    asm volatile("cp.async.cg.shared.global [%0], [%1], 16;" :: "r"(sa), "l"(g));
}
__device__ __forceinline__ uint32_t f2tf32(float f) {
    uint32_t u;
    asm("cvt.rna.tf32.f32 %0, %1;" : "=r"(u) : "f"(f));
    return u;
}
__device__ __forceinline__ void mma1688(float* d, const uint32_t* a, const uint32_t* b) {
    asm volatile(
        "mma.sync.aligned.m16n8k8.row.col.f32.tf32.tf32.f32 "
        "{%0,%1,%2,%3},{%4,%5,%6,%7},{%8,%9},{%0,%1,%2,%3};"
        : "+f"(d[0]), "+f"(d[1]), "+f"(d[2]), "+f"(d[3])
        : "r"(a[0]), "r"(a[1]), "r"(a[2]), "r"(a[3]), "r"(b[0]), "r"(b[1]));
}
__device__ __forceinline__ float gelu_tanh_f(float x) {
    return 0.5f*x*(1.f + tanhf(0.79788456080286536f*(x + 0.044715f*x*x*x)));
}

// ---------------------------------------------------------------------------
// Attention kernel: one block per (bl, h). Exact fp32.
// ---------------------------------------------------------------------------
__global__ void __launch_bounds__(256) attn_kernel(
    const float* __restrict__ img, const float* __restrict__ tit,
    const int* __restrict__ mask,
    const float* __restrict__ scale_img, const float* __restrict__ scale_tit,
    float* __restrict__ attnI, float* __restrict__ attnT)
{
    __shared__ float simg[PP][DHD+1];
    __shared__ float stit[TT][DHD+1];
    __shared__ float raw[PP][TT];
    __shared__ float pimg[PP][TT];
    __shared__ float ptit[TT][PP];
    __shared__ float sci[PP];
    __shared__ float sct[TT];
    __shared__ int   smask[TT];

    int bl = blockIdx.x >> 3;
    int h  = blockIdx.x & 7;
    int tid = threadIdx.x;

    const float* ib = img + (size_t)bl*PP*DD + h*DHD;
    const float* tb = tit + (size_t)bl*TT*DD + h*DHD;

    for (int i = tid; i < PP*DHD; i += 256) { int p=i>>6, d=i&63; simg[p][d] = ib[p*DD+d]; }
    for (int i = tid; i < TT*DHD; i += 256) { int t=i>>6, d=i&63; stit[t][d] = tb[t*DD+d]; }
    if (tid < TT) { smask[tid] = mask[bl*TT+tid]; sct[tid] = scale_tit[h*TT+tid]; }
    if (tid >= 64 && tid < 64+PP) sci[tid-64] = scale_img[h*PP + (tid-64)];
    __syncthreads();

    for (int i = tid; i < PP*TT; i += 256) {
        int p = i / TT, t = i - p*TT;
        float s = 0.f;
        #pragma unroll
        for (int d = 0; d < DHD; d++) s += simg[p][d]*stit[t][d];
        raw[p][t] = s * 0.125f;
    }
    __syncthreads();

    if (tid < PP) {
        int p = tid; float sc = sci[p];
        float v[TT]; float mx = -INFINITY;
        #pragma unroll
        for (int t = 0; t < TT; t++) { v[t] = smask[t] ? raw[p][t]*sc : -1e9f; mx = fmaxf(mx, v[t]); }
        float sum = 0.f;
        #pragma unroll
        for (int t = 0; t < TT; t++) { v[t] = __expf(v[t]-mx); sum += v[t]; }
        float inv = 1.f/sum;
        #pragma unroll
        for (int t = 0; t < TT; t++) pimg[p][t] = v[t]*inv;
    } else if (tid >= 64 && tid < 64+TT) {
        int t = tid-64; float sc = sct[t];
        if (smask[t]) {
            float mx = -INFINITY;
            for (int p = 0; p < PP; p++) mx = fmaxf(mx, raw[p][t]*sc);
            float sum = 0.f;
            for (int p = 0; p < PP; p++) { float e = __expf(raw[p][t]*sc - mx); ptit[t][p] = e; sum += e; }
            float inv = 1.f/sum;
            for (int p = 0; p < PP; p++) ptit[t][p] *= inv;
        } else {
            float u = 1.0f/(float)PP;
            for (int p = 0; p < PP; p++) ptit[t][p] = u;
        }
    }
    __syncthreads();

    for (int i = tid; i < TT*DHD; i += 256) {
        int t = i>>6, d = i&63;
        float s = 0.f;
        #pragma unroll
        for (int p = 0; p < PP; p++) s += ptit[t][p]*simg[p][d];
        attnI[((size_t)bl*TT + t)*DD + h*DHD + d] = s;
    }
    for (int i = tid; i < PP*DHD; i += 256) {
        int p = i>>6, d = i&63;
        float s = 0.f;
        #pragma unroll
        for (int t = 0; t < TT; t++) s += pimg[p][t]*stit[t][d];
        attnT[((size_t)bl*PP + p)*DD + h*DHD + d] = s;
    }
}

// ---------------------------------------------------------------------------
// tf32 mma.sync GEMM: C[M,N] = A[M,K] @ W[N,K]^T + bias (optional gelu)
// Block 256x128, 8 warps (4x2), warp tile 64x64 (4x8 of m16n8k8). BK=16,
// 4-stage cp.async ring, smem row stride 20 floats (conflict-free frag loads).
// M%256==0, N%128==0, K%16==0.
// ---------------------------------------------------------------------------
#define GBM 256
#define GBN 128
#define GBK 16
#define SSTR 20
#define STG_F ((GBM+GBN)*SSTR)       // 7680 floats per stage
#define NSTAGE 4
#define GSMEM_BYTES (NSTAGE*STG_F*4) // 122880

__device__ __forceinline__ void fill_stage(float* sA,
    const float* __restrict__ Ag, const float* __restrict__ Wg,
    int kcol, int K, int tid)
{
    float* sB = sA + GBM*SSTR;
    // A: 256 rows x 16 cols = 1024 16B chunks
    #pragma unroll
    for (int i = 0; i < 4; i++) {
        int id = tid + i*256;
        int r = id >> 2, c = (id & 3) << 2;
        cp16(sA + r*SSTR + c, Ag + (size_t)r*K + kcol + c);
    }
    // B: 128 rows x 16 cols = 512 chunks
    #pragma unroll
    for (int i = 0; i < 2; i++) {
        int id = tid + i*256;
        int r = id >> 2, c = (id & 3) << 2;
        cp16(sB + r*SSTR + c, Wg + (size_t)r*K + kcol + c);
    }
    asm volatile("cp.async.commit_group;" ::: "memory");
}

template<int GELU_EPI>
__global__ void __launch_bounds__(256, 1) gemm_mma(
    const float* __restrict__ A, const float* __restrict__ W,
    const float* __restrict__ bias, float* __restrict__ C,
    int M, int N, int K)
{
    extern __shared__ float sm[];

    int tid  = threadIdx.x;
    int warp = tid >> 5, lane = tid & 31;
    int wm = warp >> 1, wn = warp & 1;       // 4x2 warps of 64x64
    int q  = lane >> 2, t = lane & 3;
    long m0 = (long)blockIdx.y * GBM;
    long n0 = (long)blockIdx.x * GBN;

    const float* Ag = A + m0*(long)K;
    const float* Wg = W + n0*(long)K;
    const int nk = K / GBK;

    float acc[4][8][4];
    #pragma unroll
    for (int mi = 0; mi < 4; mi++)
        #pragma unroll
        for (int ni = 0; ni < 8; ni++)
            #pragma unroll
            for (int e = 0; e < 4; e++) acc[mi][ni][e] = 0.f;

    // prologue: fill 3 stages
    fill_stage(sm + 0*STG_F, Ag, Wg, 0*GBK, K, tid);
    fill_stage(sm + 1*STG_F, Ag, Wg, 1*GBK, K, tid);
    fill_stage(sm + 2*STG_F, Ag, Wg, 2*GBK, K, tid);

    for (int kt = 0; kt < nk; kt++) {
        if (kt + 3 < nk) { asm volatile("cp.async.wait_group 2;" ::: "memory"); }
        else             { asm volatile("cp.async.wait_group 0;" ::: "memory"); }
        __syncthreads();
        if (kt + 3 < nk)
            fill_stage(sm + ((kt+3)&3)*STG_F, Ag, Wg, (kt+3)*GBK, K, tid);

        const float* As_ = sm + (kt&3)*STG_F + (wm*64 + q)*SSTR + t;
        const float* Bs_ = sm + (kt&3)*STG_F + GBM*SSTR + (wn*64 + q)*SSTR + t;

        #pragma unroll
        for (int kk = 0; kk < GBK; kk += 8) {
            uint32_t a[4][4], b[8][2];
            #pragma unroll
            for (int mi = 0; mi < 4; mi++) {
                const float* p = As_ + mi*16*SSTR + kk;
                a[mi][0] = f2tf32(p[0]);
                a[mi][1] = f2tf32(p[8*SSTR]);
                a[mi][2] = f2tf32(p[4]);
                a[mi][3] = f2tf32(p[8*SSTR + 4]);
            }
            #pragma unroll
            for (int ni = 0; ni < 8; ni++) {
                const float* p = Bs_ + ni*8*SSTR + kk;
                b[ni][0] = f2tf32(p[0]);
                b[ni][1] = f2tf32(p[4]);
            }
            #pragma unroll
            for (int mi = 0; mi < 4; mi++)
                #pragma unroll
                for (int ni = 0; ni < 8; ni++)
                    mma1688(acc[mi][ni], a[mi], b[ni]);
        }
        __syncthreads();
    }

    // Epilogue: bias (+gelu), float2 stores straight from accumulators
    #pragma unroll
    for (int mi = 0; mi < 4; mi++) {
        long r0 = m0 + wm*64 + mi*16 + q;
        #pragma unroll
        for (int ni = 0; ni < 8; ni++) {
            long cc = n0 + wn*64 + ni*8 + t*2;
            float bx = bias[cc], by = bias[cc+1];
            float2 v0, v1;
            v0.x = acc[mi][ni][0] + bx;  v0.y = acc[mi][ni][1] + by;
            v1.x = acc[mi][ni][2] + bx;  v1.y = acc[mi][ni][3] + by;
            if (GELU_EPI) {
                v0.x = gelu_tanh_f(v0.x); v0.y = gelu_tanh_f(v0.y);
                v1.x = gelu_tanh_f(v1.x); v1.y = gelu_tanh_f(v1.y);
            }
            *(float2*)(C + r0*(long)N + cc)       = v0;
            *(float2*)(C + (r0+8)*(long)N + cc)   = v1;
        }
    }
}

// ---------------------------------------------------------------------------
// LayerNorm (ddof=1) + residual
// ---------------------------------------------------------------------------
__global__ void __launch_bounds__(128) ln_res_kernel(
    const float* __restrict__ F, const float* __restrict__ hid,
    const float* __restrict__ a, const float* __restrict__ b,
    float* __restrict__ out)
{
    int row = blockIdx.x;
    const float* x = F + (size_t)row*DD;
    int tid = threadIdx.x;
    float v[4]; float s = 0.f, ss = 0.f;
    #pragma unroll
    for (int k = 0; k < 4; k++) { v[k] = x[tid + k*128]; s += v[k]; ss += v[k]*v[k]; }
    #pragma unroll
    for (int o = 16; o; o >>= 1) { s += __shfl_xor_sync(~0u, s, o); ss += __shfl_xor_sync(~0u, ss, o); }
    __shared__ float sh[8];
    if ((tid & 31) == 0) { sh[tid>>5] = s; sh[4 + (tid>>5)] = ss; }
    __syncthreads();
    s  = sh[0]+sh[1]+sh[2]+sh[3];
    ss = sh[4]+sh[5]+sh[6]+sh[7];
    float mean = s * (1.f/512.f);
    float var  = fmaxf((ss - 512.f*mean*mean) * (1.f/511.f), 0.f);
    float inv  = 1.f/(sqrtf(var) + 1e-6f);
    const float* hh = hid + (size_t)row*DD;
    float* oo = out + (size_t)row*DD;
    #pragma unroll
    for (int k = 0; k < 4; k++) {
        int c = tid + k*128;
        oo[c] = hh[c] + a[c]*(v[k]-mean)*inv + b[c];
    }
}

// ---------------------------------------------------------------------------
// Launch
// ---------------------------------------------------------------------------
extern "C" void kernel_launch(void* const* d_in, const int* in_sizes, int n_in,
                              void* d_out, int out_size)
{
    const float* img         = (const float*)d_in[0];
    const float* title       = (const float*)d_in[1];
    const int*   mask        = (const int*)  d_in[2];
    const float* scale_img   = (const float*)d_in[3];
    const float* scale_title = (const float*)d_in[4];
    const float* w_proj      = (const float*)d_in[5];
    const float* b_proj      = (const float*)d_in[6];
    const float* w1_img      = (const float*)d_in[7];
    const float* b1_img      = (const float*)d_in[8];
    const float* w2_img      = (const float*)d_in[9];
    const float* b2_img      = (const float*)d_in[10];
    const float* w1_tit      = (const float*)d_in[11];
    const float* b1_tit      = (const float*)d_in[12];
    const float* w2_tit      = (const float*)d_in[13];
    const float* b2_tit      = (const float*)d_in[14];
    const float* ln_a_img    = (const float*)d_in[15];
    const float* ln_b_img    = (const float*)d_in[16];
    const float* ln_a_tit    = (const float*)d_in[17];
    const float* ln_b_tit    = (const float*)d_in[18];
    float* out = (float*)d_out;

    float *attn, *hid, *G, *F;
    cudaGetSymbolAddress((void**)&attn, g_attn);
    cudaGetSymbolAddress((void**)&hid,  g_hid);
    cudaGetSymbolAddress((void**)&G,    g_G);
    cudaGetSymbolAddress((void**)&F,    g_F);

    cudaFuncSetAttribute(gemm_mma<0>, cudaFuncAttributeMaxDynamicSharedMemorySize, GSMEM_BYTES);
    cudaFuncSetAttribute(gemm_mma<1>, cudaFuncAttributeMaxDynamicSharedMemorySize, GSMEM_BYTES);

    float* attnI = attn;
    float* attnT = attn + (size_t)M_IMG_PAD*DD;
    float* hidI  = hid;
    float* hidT  = hid + (size_t)M_IMG_PAD*DD;
    float* FI    = F;
    float* FT    = F + (size_t)M_IMG_PAD*DD;

    attn_kernel<<<NBL*HH, 256>>>(img, title, mask, scale_img, scale_title, attnI, attnT);

    // proj for both streams in one GEMM: hid = attn @ w_proj^T + b_proj
    gemm_mma<0><<<dim3(DD/GBN,  M_ALL/GBM),     256, GSMEM_BYTES>>>(attn, w_proj, b_proj, hid, M_ALL, DD, DD);

    // img FFN
    gemm_mma<1><<<dim3(DFF/GBN, M_IMG_PAD/GBM), 256, GSMEM_BYTES>>>(hidI, w1_img, b1_img, G,  M_IMG_PAD, DFF, DD);
    gemm_mma<0><<<dim3(DD/GBN,  M_IMG_PAD/GBM), 256, GSMEM_BYTES>>>(G,    w2_img, b2_img, FI, M_IMG_PAD, DD,  DFF);
    // tit FFN (reuses G)
    gemm_mma<1><<<dim3(DFF/GBN, M_TIT_PAD/GBM), 256, GSMEM_BYTES>>>(hidT, w1_tit, b1_tit, G,  M_TIT_PAD, DFF, DD);
    gemm_mma<0><<<dim3(DD/GBN,  M_TIT_PAD/GBM), 256, GSMEM_BYTES>>>(G,    w2_tit, b2_tit, FT, M_TIT_PAD, DD,  DFF);

    // LN + residual -> outputs
    ln_res_kernel<<<M_IMG, 128>>>(FI, hidI, ln_a_img, ln_b_img, out);
    ln_res_kernel<<<M_TIT, 128>>>(FT, hidT, ln_a_tit, ln_b_tit, out + (size_t)M_IMG*DD);
}

// round 5
// speedup vs baseline: 3.4834x; 1.9308x over previous
#include <cuda_runtime.h>
#include <cuda_fp16.h>
#include <cstdint>

// Problem dims
#define BB 16
#define LL 50
#define PP 49
#define TT 20
#define DD 512
#define HH 8
#define DHD 64
#define DFF 2048
#define NBL (BB*LL)            // 800
#define M_IMG (NBL*TT)         // 16000
#define M_TIT (NBL*PP)         // 39200
#define M_IMG_PAD 16128        // 63*256
#define M_TIT_PAD 39424        // 154*256
#define M_ALL (M_IMG_PAD + M_TIT_PAD)   // 55552 = 217*256

// Weight offsets in half scratch
#define WOFF_P   0
#define WOFF_1I  262144
#define WOFF_2I  1310720
#define WOFF_1T  2359296
#define WOFF_2T  3407872
#define WTOTAL   4456448

// Scratch (zero-init; pad rows never written -> stay 0)
__device__ __half g_attn_h[(size_t)M_ALL*DD];
__device__ float  g_hid  [(size_t)M_ALL*DD];
__device__ __half g_hid_h[(size_t)M_ALL*DD];
__device__ __half g_G_h  [(size_t)M_TIT_PAD*DFF];
__device__ float  g_F    [(size_t)M_ALL*DD];
__device__ __half g_Wh   [WTOTAL];

// ---------------------------------------------------------------------------
// helpers
// ---------------------------------------------------------------------------
__device__ __forceinline__ void cp16(void* s, const void* g) {
    unsigned sa = (unsigned)__cvta_generic_to_shared(s);
    asm volatile("cp.async.cg.shared.global [%0], [%1], 16;" :: "r"(sa), "l"(g));
}
__device__ __forceinline__ void ldm4(uint32_t* r, uint32_t addr) {
    asm volatile("ldmatrix.sync.aligned.m8n8.x4.shared.b16 {%0,%1,%2,%3}, [%4];"
        : "=r"(r[0]), "=r"(r[1]), "=r"(r[2]), "=r"(r[3]) : "r"(addr));
}
__device__ __forceinline__ void mma16816(float* d, const uint32_t* a, const uint32_t* b) {
    asm volatile(
        "mma.sync.aligned.m16n8k16.row.col.f32.f16.f16.f32 "
        "{%0,%1,%2,%3},{%4,%5,%6,%7},{%8,%9},{%0,%1,%2,%3};"
        : "+f"(d[0]), "+f"(d[1]), "+f"(d[2]), "+f"(d[3])
        : "r"(a[0]), "r"(a[1]), "r"(a[2]), "r"(a[3]), "r"(b[0]), "r"(b[1]));
}
__device__ __forceinline__ float gelu_tanh_f(float x) {
    return 0.5f*x*(1.f + tanhf(0.79788456080286536f*(x + 0.044715f*x*x*x)));
}

// ---------------------------------------------------------------------------
// fp32 -> fp16 convert (weights)
// ---------------------------------------------------------------------------
__global__ void __launch_bounds__(256) f2h_kernel(const float* __restrict__ s,
                                                 __half* __restrict__ d, int n)
{
    int idx = (blockIdx.x*256 + threadIdx.x) * 4;
    if (idx < n) {
        float4 v = *(const float4*)(s + idx);
        __half2* p = (__half2*)(d + idx);
        p[0] = __floats2half2_rn(v.x, v.y);
        p[1] = __floats2half2_rn(v.z, v.w);
    }
}

// ---------------------------------------------------------------------------
// Attention kernel: one block per (bl, h). fp32 math, half outputs.
// ---------------------------------------------------------------------------
__global__ void __launch_bounds__(256) attn_kernel(
    const float* __restrict__ img, const float* __restrict__ tit,
    const int* __restrict__ mask,
    const float* __restrict__ scale_img, const float* __restrict__ scale_tit,
    __half* __restrict__ attnI, __half* __restrict__ attnT)
{
    __shared__ float simg[PP][DHD+1];
    __shared__ float stit[TT][DHD+1];
    __shared__ float raw[PP][TT];
    __shared__ float pimg[PP][TT];
    __shared__ float ptit[TT][PP];
    __shared__ float sci[PP];
    __shared__ float sct[TT];
    __shared__ int   smask[TT];

    int bl = blockIdx.x >> 3;
    int h  = blockIdx.x & 7;
    int tid = threadIdx.x;

    const float* ib = img + (size_t)bl*PP*DD + h*DHD;
    const float* tb = tit + (size_t)bl*TT*DD + h*DHD;

    for (int i = tid; i < PP*DHD; i += 256) { int p=i>>6, d=i&63; simg[p][d] = ib[p*DD+d]; }
    for (int i = tid; i < TT*DHD; i += 256) { int t=i>>6, d=i&63; stit[t][d] = tb[t*DD+d]; }
    if (tid < TT) { smask[tid] = mask[bl*TT+tid]; sct[tid] = scale_tit[h*TT+tid]; }
    if (tid >= 64 && tid < 64+PP) sci[tid-64] = scale_img[h*PP + (tid-64)];
    __syncthreads();

    for (int i = tid; i < PP*TT; i += 256) {
        int p = i / TT, t = i - p*TT;
        float s = 0.f;
        #pragma unroll
        for (int d = 0; d < DHD; d++) s += simg[p][d]*stit[t][d];
        raw[p][t] = s * 0.125f;
    }
    __syncthreads();

    if (tid < PP) {
        int p = tid; float sc = sci[p];
        float v[TT]; float mx = -INFINITY;
        #pragma unroll
        for (int t = 0; t < TT; t++) { v[t] = smask[t] ? raw[p][t]*sc : -1e9f; mx = fmaxf(mx, v[t]); }
        float sum = 0.f;
        #pragma unroll
        for (int t = 0; t < TT; t++) { v[t] = __expf(v[t]-mx); sum += v[t]; }
        float inv = 1.f/sum;
        #pragma unroll
        for (int t = 0; t < TT; t++) pimg[p][t] = v[t]*inv;
    } else if (tid >= 64 && tid < 64+TT) {
        int t = tid-64; float sc = sct[t];
        if (smask[t]) {
            float mx = -INFINITY;
            for (int p = 0; p < PP; p++) mx = fmaxf(mx, raw[p][t]*sc);
            float sum = 0.f;
            for (int p = 0; p < PP; p++) { float e = __expf(raw[p][t]*sc - mx); ptit[t][p] = e; sum += e; }
            float inv = 1.f/sum;
            for (int p = 0; p < PP; p++) ptit[t][p] *= inv;
        } else {
            float u = 1.0f/(float)PP;
            for (int p = 0; p < PP; p++) ptit[t][p] = u;
        }
    }
    __syncthreads();

    for (int i = tid; i < TT*DHD; i += 256) {
        int t = i>>6, d = i&63;
        float s = 0.f;
        #pragma unroll
        for (int p = 0; p < PP; p++) s += ptit[t][p]*simg[p][d];
        attnI[((size_t)bl*TT + t)*DD + h*DHD + d] = __float2half_rn(s);
    }
    for (int i = tid; i < PP*DHD; i += 256) {
        int p = i>>6, d = i&63;
        float s = 0.f;
        #pragma unroll
        for (int t = 0; t < TT; t++) s += pimg[p][t]*stit[t][d];
        attnT[((size_t)bl*PP + p)*DD + h*DHD + d] = __float2half_rn(s);
    }
}

// ---------------------------------------------------------------------------
// fp16 mma.sync GEMM: C[M,N] = A[M,K] @ W[N,K]^T + bias
// Block 256x128, 8 warps (4x2), warp tile 64x64 (4x8 of m16n8k16). BK=32,
// 4-stage cp.async ring. Swizzled smem (16B granules, g ^= (row>>1)&3),
// operand loads via ldmatrix.x4. M%256==0, N%128==0, K%32==0.
// ---------------------------------------------------------------------------
#define GBM 256
#define GBN 128
#define GBK 32
#define STG_B 24576u                 // A 16KB + B 8KB per stage
#define NSTAGE 4
#define GSMEM_BYTES (NSTAGE*STG_B)   // 98304

__device__ __forceinline__ void fill_stage(char* sbase,
    const __half* __restrict__ Ag, const __half* __restrict__ Wg,
    int kcol, int K, int tid)
{
    // A: 256 rows x 4 granules (16B = 8 halves)
    #pragma unroll
    for (int i = 0; i < 4; i++) {
        int id = tid + i*256;
        int r = id >> 2, g = id & 3;
        uint32_t off = (uint32_t)((r*4 + (g ^ ((r>>1)&3))) << 4);
        cp16(sbase + off, Ag + (size_t)r*K + kcol + g*8);
    }
    // B: 128 rows x 4 granules
    #pragma unroll
    for (int i = 0; i < 2; i++) {
        int id = tid + i*256;
        int r = id >> 2, g = id & 3;
        uint32_t off = 16384u + (uint32_t)((r*4 + (g ^ ((r>>1)&3))) << 4);
        cp16(sbase + off, Wg + (size_t)r*K + kcol + g*8);
    }
    asm volatile("cp.async.commit_group;" ::: "memory");
}

template<int WF32, int WH, int GELU_EPI>
__global__ void __launch_bounds__(256, 1) gemm_h(
    const __half* __restrict__ A, const __half* __restrict__ W,
    const float* __restrict__ bias, float* __restrict__ C,
    __half* __restrict__ Ch, int M, int N, int K)
{
    extern __shared__ __align__(1024) char sm[];
    uint32_t smem_base = (uint32_t)__cvta_generic_to_shared(sm);

    int tid  = threadIdx.x;
    int warp = tid >> 5, lane = tid & 31;
    int wm = warp >> 1, wn = warp & 1;       // 4x2 warps of 64x64
    int q  = lane >> 2, t = lane & 3;
    long m0 = (long)blockIdx.y * GBM;
    long n0 = (long)blockIdx.x * GBN;

    const __half* Ag = A + m0*(long)K;
    const __half* Wg = W + n0*(long)K;
    const int nk = K / GBK;

    // per-lane ldmatrix address components
    int a_rl = lane & 15;                 // row within 16-row tile
    int a_gs = lane >> 4;                 // k-granule select (0/1)
    int a_sx = (a_rl >> 1) & 3;
    int b_nl = (lane & 7) | ((lane & 16) >> 1);   // n within 16-col tile
    int b_gs = (lane >> 3) & 1;
    int b_sx = (b_nl >> 1) & 3;

    float acc[4][8][4];
    #pragma unroll
    for (int mi = 0; mi < 4; mi++)
        #pragma unroll
        for (int ni = 0; ni < 8; ni++)
            #pragma unroll
            for (int e = 0; e < 4; e++) acc[mi][ni][e] = 0.f;

    // prologue: fill 3 stages
    fill_stage(sm + 0*STG_B, Ag, Wg, 0*GBK, K, tid);
    fill_stage(sm + 1*STG_B, Ag, Wg, 1*GBK, K, tid);
    fill_stage(sm + 2*STG_B, Ag, Wg, 2*GBK, K, tid);

    for (int kt = 0; kt < nk; kt++) {
        if (kt + 3 < nk) { asm volatile("cp.async.wait_group 2;" ::: "memory"); }
        else             { asm volatile("cp.async.wait_group 0;" ::: "memory"); }
        __syncthreads();
        if (kt + 3 < nk)
            fill_stage(sm + ((kt+3)&3)*STG_B, Ag, Wg, (kt+3)*GBK, K, tid);

        uint32_t sa = smem_base + (uint32_t)(kt&3)*STG_B;
        uint32_t sb = sa + 16384u;

        #pragma unroll
        for (int ks = 0; ks < 2; ks++) {
            uint32_t a[4][4], b[4][4];
            #pragma unroll
            for (int mi = 0; mi < 4; mi++) {
                int r = wm*64 + mi*16 + a_rl;
                uint32_t addr = sa + (uint32_t)(((r*4) + ((ks*2 + a_gs) ^ a_sx)) << 4);
                ldm4(a[mi], addr);
            }
            #pragma unroll
            for (int j = 0; j < 4; j++) {
                int n = wn*64 + j*16 + b_nl;
                uint32_t addr = sb + (uint32_t)(((n*4) + ((ks*2 + b_gs) ^ b_sx)) << 4);
                ldm4(b[j], addr);
            }
            #pragma unroll
            for (int mi = 0; mi < 4; mi++)
                #pragma unroll
                for (int ni = 0; ni < 8; ni++)
                    mma16816(acc[mi][ni], a[mi], &b[ni>>1][(ni&1)*2]);
        }
        __syncthreads();
    }

    // Epilogue: bias (+gelu) straight from accumulators
    #pragma unroll
    for (int mi = 0; mi < 4; mi++) {
        long r0 = m0 + wm*64 + mi*16 + q;
        #pragma unroll
        for (int ni = 0; ni < 8; ni++) {
            long cc = n0 + wn*64 + ni*8 + t*2;
            float bx = bias[cc], by = bias[cc+1];
            float v00 = acc[mi][ni][0] + bx, v01 = acc[mi][ni][1] + by;
            float v10 = acc[mi][ni][2] + bx, v11 = acc[mi][ni][3] + by;
            if (GELU_EPI) {
                v00 = gelu_tanh_f(v00); v01 = gelu_tanh_f(v01);
                v10 = gelu_tanh_f(v10); v11 = gelu_tanh_f(v11);
            }
            if (WF32) {
                *(float2*)(C + r0*(long)N + cc)     = make_float2(v00, v01);
                *(float2*)(C + (r0+8)*(long)N + cc) = make_float2(v10, v11);
            }
            if (WH) {
                *(__half2*)(Ch + r0*(long)N + cc)     = __floats2half2_rn(v00, v01);
                *(__half2*)(Ch + (r0+8)*(long)N + cc) = __floats2half2_rn(v10, v11);
            }
        }
    }
}

// ---------------------------------------------------------------------------
// LayerNorm (ddof=1) + residual
// ---------------------------------------------------------------------------
__global__ void __launch_bounds__(128) ln_res_kernel(
    const float* __restrict__ F, const float* __restrict__ hid,
    const float* __restrict__ a, const float* __restrict__ b,
    float* __restrict__ out)
{
    int row = blockIdx.x;
    const float* x = F + (size_t)row*DD;
    int tid = threadIdx.x;
    float v[4]; float s = 0.f, ss = 0.f;
    #pragma unroll
    for (int k = 0; k < 4; k++) { v[k] = x[tid + k*128]; s += v[k]; ss += v[k]*v[k]; }
    #pragma unroll
    for (int o = 16; o; o >>= 1) { s += __shfl_xor_sync(~0u, s, o); ss += __shfl_xor_sync(~0u, ss, o); }
    __shared__ float sh[8];
    if ((tid & 31) == 0) { sh[tid>>5] = s; sh[4 + (tid>>5)] = ss; }
    __syncthreads();
    s  = sh[0]+sh[1]+sh[2]+sh[3];
    ss = sh[4]+sh[5]+sh[6]+sh[7];
    float mean = s * (1.f/512.f);
    float var  = fmaxf((ss - 512.f*mean*mean) * (1.f/511.f), 0.f);
    float inv  = 1.f/(sqrtf(var) + 1e-6f);
    const float* hh = hid + (size_t)row*DD;
    float* oo = out + (size_t)row*DD;
    #pragma unroll
    for (int k = 0; k < 4; k++) {
        int c = tid + k*128;
        oo[c] = hh[c] + a[c]*(v[k]-mean)*inv + b[c];
    }
}

// ---------------------------------------------------------------------------
// Launch
// ---------------------------------------------------------------------------
extern "C" void kernel_launch(void* const* d_in, const int* in_sizes, int n_in,
                              void* d_out, int out_size)
{
    const float* img         = (const float*)d_in[0];
    const float* title       = (const float*)d_in[1];
    const int*   mask        = (const int*)  d_in[2];
    const float* scale_img   = (const float*)d_in[3];
    const float* scale_title = (const float*)d_in[4];
    const float* w_proj      = (const float*)d_in[5];
    const float* b_proj      = (const float*)d_in[6];
    const float* w1_img      = (const float*)d_in[7];
    const float* b1_img      = (const float*)d_in[8];
    const float* w2_img      = (const float*)d_in[9];
    const float* b2_img      = (const float*)d_in[10];
    const float* w1_tit      = (const float*)d_in[11];
    const float* b1_tit      = (const float*)d_in[12];
    const float* w2_tit      = (const float*)d_in[13];
    const float* b2_tit      = (const float*)d_in[14];
    const float* ln_a_img    = (const float*)d_in[15];
    const float* ln_b_img    = (const float*)d_in[16];
    const float* ln_a_tit    = (const float*)d_in[17];
    const float* ln_b_tit    = (const float*)d_in[18];
    float* out = (float*)d_out;

    __half *attn_h, *hid_h, *G_h, *Wh;
    float  *hid, *F;
    cudaGetSymbolAddress((void**)&attn_h, g_attn_h);
    cudaGetSymbolAddress((void**)&hid,    g_hid);
    cudaGetSymbolAddress((void**)&hid_h,  g_hid_h);
    cudaGetSymbolAddress((void**)&G_h,    g_G_h);
    cudaGetSymbolAddress((void**)&F,      g_F);
    cudaGetSymbolAddress((void**)&Wh,     g_Wh);

    cudaFuncSetAttribute(gemm_h<1,1,0>, cudaFuncAttributeMaxDynamicSharedMemorySize, GSMEM_BYTES);
    cudaFuncSetAttribute(gemm_h<0,1,1>, cudaFuncAttributeMaxDynamicSharedMemorySize, GSMEM_BYTES);
    cudaFuncSetAttribute(gemm_h<1,0,0>, cudaFuncAttributeMaxDynamicSharedMemorySize, GSMEM_BYTES);

    // convert weights to half
    f2h_kernel<<<(262144/4+255)/256,  256>>>(w_proj, Wh + WOFF_P,  262144);
    f2h_kernel<<<(1048576/4+255)/256, 256>>>(w1_img, Wh + WOFF_1I, 1048576);
    f2h_kernel<<<(1048576/4+255)/256, 256>>>(w2_img, Wh + WOFF_2I, 1048576);
    f2h_kernel<<<(1048576/4+255)/256, 256>>>(w1_tit, Wh + WOFF_1T, 1048576);
    f2h_kernel<<<(1048576/4+255)/256, 256>>>(w2_tit, Wh + WOFF_2T, 1048576);

    __half* attnI = attn_h;
    __half* attnT = attn_h + (size_t)M_IMG_PAD*DD;
    float*  hidI  = hid;
    __half* hidIh = hid_h;
    __half* hidTh = hid_h + (size_t)M_IMG_PAD*DD;
    float*  FI    = F;
    float*  FT    = F + (size_t)M_IMG_PAD*DD;

    attn_kernel<<<NBL*HH, 256>>>(img, title, mask, scale_img, scale_title, attnI, attnT);

    // proj for both streams: hid(f32) + hid(h) = attn @ w_proj^T + b_proj
    gemm_h<1,1,0><<<dim3(DD/GBN,  M_ALL/GBM),     256, GSMEM_BYTES>>>(attn_h, Wh+WOFF_P,  b_proj, hid,  hid_h, M_ALL,     DD,  DD);

    // img FFN
    gemm_h<0,1,1><<<dim3(DFF/GBN, M_IMG_PAD/GBM), 256, GSMEM_BYTES>>>(hidIh,  Wh+WOFF_1I, b1_img, 0,    G_h,   M_IMG_PAD, DFF, DD);
    gemm_h<1,0,0><<<dim3(DD/GBN,  M_IMG_PAD/GBM), 256, GSMEM_BYTES>>>(G_h,    Wh+WOFF_2I, b2_img, FI,   0,     M_IMG_PAD, DD,  DFF);
    // tit FFN (reuses G_h)
    gemm_h<0,1,1><<<dim3(DFF/GBN, M_TIT_PAD/GBM), 256, GSMEM_BYTES>>>(hidTh,  Wh+WOFF_1T, b1_tit, 0,    G_h,   M_TIT_PAD, DFF, DD);
    gemm_h<1,0,0><<<dim3(DD/GBN,  M_TIT_PAD/GBM), 256, GSMEM_BYTES>>>(G_h,    Wh+WOFF_2T, b2_tit, FT,   0,     M_TIT_PAD, DD,  DFF);

    // LN + residual -> outputs
    ln_res_kernel<<<M_IMG, 128>>>(FI, hid, ln_a_img, ln_b_img, out);
    ln_res_kernel<<<M_TIT, 128>>>(FT, hid + (size_t)M_IMG_PAD*DD, ln_a_tit, ln_b_tit, out + (size_t)M_IMG*DD);
}